// round 9
// baseline (speedup 1.0000x reference)
#include <cuda_runtime.h>
#include <cstdint>

// ACoef: per-sample traces of x^2..x^11 for 65536 16x16 fp32 matrices,
// out[b] = sum_{i,j} coef[i][j] * tr_{i+2}^(j+1) / 256^(i+j+1).
//
// One sample per WARP, tensor-core mma m16n8k8 tf32, 3xTF32 compensation.
// Chain: x2=X*X, x3=X*x2, x5=x3*x2, x6=x3*x3 (A-frag(x3) free from T3,
// since A-frag(M) == B-frag(M^T)). tr2,tr3 diagonals; rest are frag dots.
// R9: __launch_bounds__(128, 8) caps regs at 64 -> occ 39%->~50% (R8 was
// latency-bound at issue=59% with all pipes <55%); poly butterfly 4 shfl.

__device__ __forceinline__ void split_tf32(float v, uint32_t& hi, uint32_t& lo) {
    hi = __float_as_uint(v) & 0xFFFFE000u;
    lo = __float_as_uint(v - __uint_as_float(hi));
}
__device__ __forceinline__ void mma_tf32(float d[4], const uint32_t a[4],
                                         const uint32_t b[2], const float c[4]) {
    asm volatile(
        "mma.sync.aligned.m16n8k8.row.col.f32.tf32.tf32.f32 "
        "{%0,%1,%2,%3}, {%4,%5,%6,%7}, {%8,%9}, {%10,%11,%12,%13};"
        : "=f"(d[0]), "=f"(d[1]), "=f"(d[2]), "=f"(d[3])
        : "r"(a[0]), "r"(a[1]), "r"(a[2]), "r"(a[3]),
          "r"(b[0]), "r"(b[1]),
          "f"(c[0]), "f"(c[1]), "f"(c[2]), "f"(c[3]));
}
__device__ __forceinline__ float shfl(float v, int src) {
    return __shfl_sync(0xffffffffu, v, src);
}

// C-fragment of a 16x16 fp32 matrix: CH[nn][4], nn = n-half (cols 8nn..8nn+7).
// Lane (g = lane>>2, t = lane&3):
//   CH[nn][0] = M[g  ][8nn+2t]   CH[nn][1] = M[g  ][8nn+2t+1]
//   CH[nn][2] = M[g+8][8nn+2t]   CH[nn][3] = M[g+8][8nn+2t+1]
// Element M[R][C]: lane (R&7)*4 + ((C&7)>>1), reg CH[C>>3][2*(R>>3)+(C&1)].

// C-frag -> col-major B-frags (tf32 hi/lo), pre-staged single-shfl scheme.
__device__ __forceinline__ void conv_to_B(const float CH[2][4], int idxA, int idxB,
                                          bool godd, bool hi16,
                                          uint32_t Bhi[2][2][2], uint32_t Blo[2][2][2]) {
#pragma unroll
    for (int nn = 0; nn < 2; nn++)
#pragma unroll
        for (int kk = 0; kk < 2; kk++) {
            float z1 = hi16 ? CH[nn][2 * kk + 1] : CH[nn][2 * kk];
            float s1 = shfl(z1, idxA);
            float z2 = hi16 ? CH[nn][2 * kk] : CH[nn][2 * kk + 1];
            float s2 = shfl(z2, idxB);
            float b0 = godd ? s2 : s1;
            float b1 = godd ? s1 : s2;
            split_tf32(b0, Bhi[kk][nn][0], Blo[kk][nn][0]);
            split_tf32(b1, Bhi[kk][nn][1], Blo[kk][nn][1]);
        }
}

// Register transpose: TH = C-frag layout of M^T given CH of M (pre-staged).
__device__ __forceinline__ void transpose_frag(const float CH[2][4], int idxA, int idxB,
                                               bool godd, float TH[2][4]) {
#pragma unroll
    for (int nn = 0; nn < 2; nn++)
#pragma unroll
        for (int h = 0; h < 2; h++) {
            float z1 = godd ? CH[h][2 * nn + 1] : CH[h][2 * nn];
            float s1 = shfl(z1, idxA);
            float z2 = godd ? CH[h][2 * nn] : CH[h][2 * nn + 1];
            float s2 = shfl(z2, idxB);
            TH[nn][2 * h + 0] = godd ? s2 : s1;
            TH[nn][2 * h + 1] = godd ? s1 : s2;
        }
}

// Closed-form diag partial: lane holds diagonal elems iff t == g>>1.
__device__ __forceinline__ float diag_partial(const float CH[2][4], bool isdiag, bool godd) {
    float e0 = godd ? CH[0][1] : CH[0][0];
    float e1 = godd ? CH[1][3] : CH[1][2];
    return isdiag ? (e0 + e1) : 0.f;
}

// <A, B> over fragment positions; frag_dot(T_p, C_q) = tr(x^p * x^q) partial.
__device__ __forceinline__ float frag_dot(const float A[2][4], const float B[2][4]) {
    float s = 0.f;
#pragma unroll
    for (int nn = 0; nn < 2; nn++)
#pragma unroll
        for (int r = 0; r < 4; r++) s = fmaf(A[nn][r], B[nn][r], s);
    return s;
}

__device__ __forceinline__ void mm_chain(const uint32_t Ahi[2][4], const uint32_t Alo[2][4],
                                         const uint32_t Bhi[2][2][2], const uint32_t Blo[2][2][2],
                                         float D[2][4]) {
#pragma unroll
    for (int nn = 0; nn < 2; nn++) {
        float d[4] = {0.f, 0.f, 0.f, 0.f};
#pragma unroll
        for (int kk = 0; kk < 2; kk++) {
            mma_tf32(d, Ahi[kk], Blo[kk][nn], d);
            mma_tf32(d, Alo[kk], Bhi[kk][nn], d);
            mma_tf32(d, Ahi[kk], Bhi[kk][nn], d);
        }
#pragma unroll
        for (int r = 0; r < 4; r++) D[nn][r] = d[r];
    }
}

__global__ void __launch_bounds__(128, 8)
acoef_kernel(const float* __restrict__ x, const float* __restrict__ coef,
             float* __restrict__ out, int nsamples) {
    const int lane = threadIdx.x & 31;
    const int g = lane >> 2;
    const int t = lane & 3;
    const int q = g >> 1;
    const bool godd = (g & 1);
    const bool hi16 = (lane & 16);
    const bool isdiag = (t == q);

    const int idxA_c = 4 * t + q + (godd ? 16 : 0);   // conv
    const int idxB_c = idxA_c ^ 16;
    const int idxA_t = 8 * t + q + (godd ? 4 : 0);    // transpose
    const int idxB_t = idxA_t ^ 4;

    const long sample = (long)blockIdx.x * (blockDim.x >> 5) + (threadIdx.x >> 5);
    if (sample >= nsamples) return;
    const float* gx = x + sample * 256;

    // ---- load X fragments: A row-major + B col-major, tf32 split ----
    uint32_t AXhi[2][4], AXlo[2][4];
#pragma unroll
    for (int kk = 0; kk < 2; kk++) {
#pragma unroll
        for (int idx = 0; idx < 4; idx++) {
            int row = g + 8 * (idx & 1);
            int col = 8 * kk + t + 4 * (idx >> 1);
            float v = __ldg(gx + row * 16 + col);
            split_tf32(v, AXhi[kk][idx], AXlo[kk][idx]);
        }
    }
    uint32_t BXhi[2][2][2], BXlo[2][2][2];
#pragma unroll
    for (int kk = 0; kk < 2; kk++)
#pragma unroll
        for (int nn = 0; nn < 2; nn++) {
            float b0 = __ldg(gx + (8 * kk + t) * 16 + 8 * nn + g);
            float b1 = __ldg(gx + (8 * kk + t + 4) * 16 + 8 * nn + g);
            split_tf32(b0, BXhi[kk][nn][0], BXlo[kk][nn][0]);
            split_tf32(b1, BXhi[kk][nn][1], BXlo[kk][nn][1]);
        }

    float V[16];   // V[i] = partial of tr(x^{i+2}); pad to 16 for reduce-scatter
#pragma unroll
    for (int i = 10; i < 16; i++) V[i] = 0.f;

    float C2[2][4], C3[2][4], C5[2][4], C6[2][4];
    float T2[2][4], T3[2][4], T5[2][4];

    // mm1: x2 = X*X
    mm_chain(AXhi, AXlo, BXhi, BXlo, C2);
    V[0] = diag_partial(C2, isdiag, godd);          // tr2

    // B(x2) + T2; tr4 = <T2, C2>; C2 dead after
    uint32_t Bc2hi[2][2][2], Bc2lo[2][2][2];
    conv_to_B(C2, idxA_c, idxB_c, godd, hi16, Bc2hi, Bc2lo);
    transpose_frag(C2, idxA_t, idxB_t, godd, T2);
    V[2] = frag_dot(T2, C2);                        // tr4

    // mm2: x3 = X*x2   (A(X), B(X) dead after)
    mm_chain(AXhi, AXlo, Bc2hi, Bc2lo, C3);
    V[1] = diag_partial(C3, isdiag, godd);          // tr3
    V[3] = frag_dot(T2, C3);                        // tr5 = tr(x2*x3)

    // T3; tr6 = <T3, C3>; A(x3) = conv(T3) (A-frag(M) == B-frag(M^T))
    transpose_frag(C3, idxA_t, idxB_t, godd, T3);
    V[4] = frag_dot(T3, C3);                        // tr6 = tr(x3*x3)

    uint32_t Bt3hi[2][2][2], Bt3lo[2][2][2];
    conv_to_B(T3, idxA_c, idxB_c, godd, hi16, Bt3hi, Bt3lo);
    uint32_t A3hi[2][4], A3lo[2][4];
#pragma unroll
    for (int kk = 0; kk < 2; kk++) {
        A3hi[kk][0] = Bt3hi[kk][0][0]; A3hi[kk][1] = Bt3hi[kk][1][0];
        A3hi[kk][2] = Bt3hi[kk][0][1]; A3hi[kk][3] = Bt3hi[kk][1][1];
        A3lo[kk][0] = Bt3lo[kk][0][0]; A3lo[kk][1] = Bt3lo[kk][1][0];
        A3lo[kk][2] = Bt3lo[kk][0][1]; A3lo[kk][3] = Bt3lo[kk][1][1];
    }

    // mm3: x5 = x3*x2   (Bc2 dead after)
    mm_chain(A3hi, A3lo, Bc2hi, Bc2lo, C5);
    V[5] = frag_dot(T2, C5);                        // tr7 = tr(x2*x5); T2 dead
    V[6] = frag_dot(T3, C5);                        // tr8 = tr(x3*x5)

    // B(x3) deferred until here (C3 kept live instead of 16-reg Bc3)
    uint32_t Bc3hi[2][2][2], Bc3lo[2][2][2];
    conv_to_B(C3, idxA_c, idxB_c, godd, hi16, Bc3hi, Bc3lo);

    // mm4: x6 = x3*x3   (A3, Bc3 dead after)
    mm_chain(A3hi, A3lo, Bc3hi, Bc3lo, C6);

    transpose_frag(C5, idxA_t, idxB_t, godd, T5);
    V[8] = frag_dot(T5, C5);                        // tr10 = tr(x5*x5)
    V[7] = frag_dot(T3, C6);                        // tr9  = tr(x3*x6); T3 dead
    V[9] = frag_dot(T5, C6);                        // tr11 = tr(x5*x6)

    // ---- recursive-halving reduce-scatter over 32 lanes ----
    // After: lane L holds the full sum of trace index (L>>1)&15.
    {
        const bool h16b = (lane & 16);
#pragma unroll
        for (int k = 0; k < 8; k++) {
            float send = h16b ? V[k] : V[k + 8];
            float recv = __shfl_xor_sync(0xffffffffu, send, 16);
            V[k] = (h16b ? V[k + 8] : V[k]) + recv;
        }
        const bool h8 = (lane & 8);
#pragma unroll
        for (int k = 0; k < 4; k++) {
            float send = h8 ? V[k] : V[k + 4];
            float recv = __shfl_xor_sync(0xffffffffu, send, 8);
            V[k] = (h8 ? V[k + 4] : V[k]) + recv;
        }
        const bool h4 = (lane & 4);
#pragma unroll
        for (int k = 0; k < 2; k++) {
            float send = h4 ? V[k] : V[k + 2];
            float recv = __shfl_xor_sync(0xffffffffu, send, 4);
            V[k] = (h4 ? V[k + 2] : V[k]) + recv;
        }
        {
            const bool h2 = (lane & 2);
            float send = h2 ? V[0] : V[1];
            float recv = __shfl_xor_sync(0xffffffffu, send, 2);
            V[0] = (h2 ? V[1] : V[0]) + recv;
        }
        V[0] += __shfl_xor_sync(0xffffffffu, V[0], 1);
    }

    // ---- distributed polynomial: lane holding trace i computes row i ----
    {
        const int i = (lane >> 1) & 15;
        const bool active = (lane < 20) && ((lane & 1) == 0);
        const int ic = (i < 10) ? i : 0;
        const float4 cf = __ldg((const float4*)coef + ic);
        const float u  = V[0] * (1.0f / 256.0f);
        const float u2 = u * u;
        float term = cf.x * u + cf.y * u2 + cf.z * (u2 * u) + cf.w * (u2 * u2);
        term *= __uint_as_float((uint32_t)(127 - 8 * i) << 23);   // 256^{-i}
        term = active ? term : 0.f;
        // terms live only in even lanes < 20 -> offsets 16,8,4,2 suffice
        term += __shfl_xor_sync(0xffffffffu, term, 16);
        term += __shfl_xor_sync(0xffffffffu, term, 8);
        term += __shfl_xor_sync(0xffffffffu, term, 4);
        term += __shfl_xor_sync(0xffffffffu, term, 2);
        if (lane == 0) out[sample] = term;
    }
}

extern "C" void kernel_launch(void* const* d_in, const int* in_sizes, int n_in,
                              void* d_out, int out_size) {
    const float* x;
    const float* coef;
    if (n_in >= 2 && in_sizes[0] == 40) {
        coef = (const float*)d_in[0];
        x    = (const float*)d_in[1];
    } else {
        x    = (const float*)d_in[0];
        coef = (const float*)d_in[1];
    }
    float* out = (float*)d_out;
    int nsamples = out_size;
    const int warps_per_cta = 4;
    int grid = (nsamples + warps_per_cta - 1) / warps_per_cta;
    acoef_kernel<<<grid, warps_per_cta * 32>>>(x, coef, out, nsamples);
}

// round 10
// speedup vs baseline: 1.0572x; 1.0572x over previous
#include <cuda_runtime.h>
#include <cstdint>

// ACoef: per-sample traces of x^2..x^11 for 65536 16x16 fp32 matrices,
// out[b] = sum_{i,j} coef[i][j] * tr_{i+2}^(j+1) / 256^(i+j+1).
//
// One sample per WARP, tensor-core mma m16n8k8 tf32, 3xTF32 compensation.
// Chain: x2=X*X, x3=X*x2, x5=x3*x2, x6=x3*x3 (A-frag(x3) free from T3).
// R10: Y = C-frag(X^T) loaded straight from gmem (no shfl/split) gives
// tr(x^{q+1}) = <Y, C_q> -> T2 eliminated; tr5/tr6 via diagonals.
// Reduce-scatter redesigned 5/3/2/1/1 (12 shfl); poly butterfly 4 shfl.
// Launch bounds reverted to plain 128 (R9's reg cap caused remat regression).

__device__ __forceinline__ void split_tf32(float v, uint32_t& hi, uint32_t& lo) {
    hi = __float_as_uint(v) & 0xFFFFE000u;
    lo = __float_as_uint(v - __uint_as_float(hi));
}
__device__ __forceinline__ void mma_tf32(float d[4], const uint32_t a[4],
                                         const uint32_t b[2], const float c[4]) {
    asm volatile(
        "mma.sync.aligned.m16n8k8.row.col.f32.tf32.tf32.f32 "
        "{%0,%1,%2,%3}, {%4,%5,%6,%7}, {%8,%9}, {%10,%11,%12,%13};"
        : "=f"(d[0]), "=f"(d[1]), "=f"(d[2]), "=f"(d[3])
        : "r"(a[0]), "r"(a[1]), "r"(a[2]), "r"(a[3]),
          "r"(b[0]), "r"(b[1]),
          "f"(c[0]), "f"(c[1]), "f"(c[2]), "f"(c[3]));
}
__device__ __forceinline__ float shfl(float v, int src) {
    return __shfl_sync(0xffffffffu, v, src);
}

// C-fragment of a 16x16 fp32 matrix: CH[nn][4], nn = n-half (cols 8nn..8nn+7).
// Lane (g = lane>>2, t = lane&3):
//   CH[nn][0] = M[g  ][8nn+2t]   CH[nn][1] = M[g  ][8nn+2t+1]
//   CH[nn][2] = M[g+8][8nn+2t]   CH[nn][3] = M[g+8][8nn+2t+1]

// C-frag -> col-major B-frags (tf32 hi/lo), pre-staged single-shfl scheme.
__device__ __forceinline__ void conv_to_B(const float CH[2][4], int idxA, int idxB,
                                          bool godd, bool hi16,
                                          uint32_t Bhi[2][2][2], uint32_t Blo[2][2][2]) {
#pragma unroll
    for (int nn = 0; nn < 2; nn++)
#pragma unroll
        for (int kk = 0; kk < 2; kk++) {
            float z1 = hi16 ? CH[nn][2 * kk + 1] : CH[nn][2 * kk];
            float s1 = shfl(z1, idxA);
            float z2 = hi16 ? CH[nn][2 * kk] : CH[nn][2 * kk + 1];
            float s2 = shfl(z2, idxB);
            float b0 = godd ? s2 : s1;
            float b1 = godd ? s1 : s2;
            split_tf32(b0, Bhi[kk][nn][0], Blo[kk][nn][0]);
            split_tf32(b1, Bhi[kk][nn][1], Blo[kk][nn][1]);
        }
}

// Register transpose: TH = C-frag layout of M^T given CH of M (pre-staged).
__device__ __forceinline__ void transpose_frag(const float CH[2][4], int idxA, int idxB,
                                               bool godd, float TH[2][4]) {
#pragma unroll
    for (int nn = 0; nn < 2; nn++)
#pragma unroll
        for (int h = 0; h < 2; h++) {
            float z1 = godd ? CH[h][2 * nn + 1] : CH[h][2 * nn];
            float s1 = shfl(z1, idxA);
            float z2 = godd ? CH[h][2 * nn] : CH[h][2 * nn + 1];
            float s2 = shfl(z2, idxB);
            TH[nn][2 * h + 0] = godd ? s2 : s1;
            TH[nn][2 * h + 1] = godd ? s1 : s2;
        }
}

// Closed-form diag partial: lane holds diagonal elems iff t == g>>1.
__device__ __forceinline__ float diag_partial(const float CH[2][4], bool isdiag, bool godd) {
    float e0 = godd ? CH[0][1] : CH[0][0];
    float e1 = godd ? CH[1][3] : CH[1][2];
    return isdiag ? (e0 + e1) : 0.f;
}

// <A, B> elementwise over fragment positions.
// frag_dot(T_p, C_q) = tr(x^p x^q); frag_dot(Y, C_q) = tr(x^{q+1}).
__device__ __forceinline__ float frag_dot(const float A[2][4], const float B[2][4]) {
    float s = 0.f;
#pragma unroll
    for (int nn = 0; nn < 2; nn++)
#pragma unroll
        for (int r = 0; r < 4; r++) s = fmaf(A[nn][r], B[nn][r], s);
    return s;
}

__device__ __forceinline__ void mm_chain(const uint32_t Ahi[2][4], const uint32_t Alo[2][4],
                                         const uint32_t Bhi[2][2][2], const uint32_t Blo[2][2][2],
                                         float D[2][4]) {
#pragma unroll
    for (int nn = 0; nn < 2; nn++) {
        float d[4] = {0.f, 0.f, 0.f, 0.f};
#pragma unroll
        for (int kk = 0; kk < 2; kk++) {
            mma_tf32(d, Ahi[kk], Blo[kk][nn], d);
            mma_tf32(d, Alo[kk], Bhi[kk][nn], d);
            mma_tf32(d, Ahi[kk], Bhi[kk][nn], d);
        }
#pragma unroll
        for (int r = 0; r < 4; r++) D[nn][r] = d[r];
    }
}

__global__ void __launch_bounds__(128)
acoef_kernel(const float* __restrict__ x, const float* __restrict__ coef,
             float* __restrict__ out, int nsamples) {
    const int lane = threadIdx.x & 31;
    const int g = lane >> 2;
    const int t = lane & 3;
    const int q = g >> 1;
    const bool godd = (g & 1);
    const bool hi16 = (lane & 16);
    const bool isdiag = (t == q);

    const int idxA_c = 4 * t + q + (godd ? 16 : 0);   // conv
    const int idxB_c = idxA_c ^ 16;
    const int idxA_t = 8 * t + q + (godd ? 4 : 0);    // transpose
    const int idxB_t = idxA_t ^ 4;

    const long sample = (long)blockIdx.x * (blockDim.x >> 5) + (threadIdx.x >> 5);
    if (sample >= nsamples) return;
    const float* gx = x + sample * 256;

    // ---- load X fragments: A row-major + B col-major (tf32 split) ----
    uint32_t AXhi[2][4], AXlo[2][4];
#pragma unroll
    for (int kk = 0; kk < 2; kk++) {
#pragma unroll
        for (int idx = 0; idx < 4; idx++) {
            int row = g + 8 * (idx & 1);
            int col = 8 * kk + t + 4 * (idx >> 1);
            float v = __ldg(gx + row * 16 + col);
            split_tf32(v, AXhi[kk][idx], AXlo[kk][idx]);
        }
    }
    uint32_t BXhi[2][2][2], BXlo[2][2][2];
#pragma unroll
    for (int kk = 0; kk < 2; kk++)
#pragma unroll
        for (int nn = 0; nn < 2; nn++) {
            float b0 = __ldg(gx + (8 * kk + t) * 16 + 8 * nn + g);
            float b1 = __ldg(gx + (8 * kk + t + 4) * 16 + 8 * nn + g);
            split_tf32(b0, BXhi[kk][nn][0], BXlo[kk][nn][0]);
            split_tf32(b1, BXhi[kk][nn][1], BXlo[kk][nn][1]);
        }
    // ---- Y = C-frag(X^T), raw fp32, dots only (no split, no shfl) ----
    float Y[2][4];
#pragma unroll
    for (int nn = 0; nn < 2; nn++) {
        Y[nn][0] = __ldg(gx + (8 * nn + 2 * t)     * 16 + g);
        Y[nn][1] = __ldg(gx + (8 * nn + 2 * t + 1) * 16 + g);
        Y[nn][2] = __ldg(gx + (8 * nn + 2 * t)     * 16 + g + 8);
        Y[nn][3] = __ldg(gx + (8 * nn + 2 * t + 1) * 16 + g + 8);
    }

    float V[10];   // V[i] = per-lane partial of tr(x^{i+2})
    float C2[2][4], C3[2][4], C5[2][4], C6[2][4];
    float T3[2][4], T5[2][4];

    // mm1: x2 = X*X
    mm_chain(AXhi, AXlo, BXhi, BXlo, C2);
    V[0] = diag_partial(C2, isdiag, godd);          // tr2

    // B(x2); C2 dead after
    uint32_t Bc2hi[2][2][2], Bc2lo[2][2][2];
    conv_to_B(C2, idxA_c, idxB_c, godd, hi16, Bc2hi, Bc2lo);

    // mm2: x3 = X*x2   (A(X), B(X) dead after)
    mm_chain(AXhi, AXlo, Bc2hi, Bc2lo, C3);
    V[1] = diag_partial(C3, isdiag, godd);          // tr3
    V[2] = frag_dot(Y, C3);                         // tr4 = tr(x*x3)

    // T3; A(x3) = conv(T3) (A-frag(M) == B-frag(M^T))
    transpose_frag(C3, idxA_t, idxB_t, godd, T3);
    uint32_t Bt3hi[2][2][2], Bt3lo[2][2][2];
    conv_to_B(T3, idxA_c, idxB_c, godd, hi16, Bt3hi, Bt3lo);
    uint32_t A3hi[2][4], A3lo[2][4];
#pragma unroll
    for (int kk = 0; kk < 2; kk++) {
        A3hi[kk][0] = Bt3hi[kk][0][0]; A3hi[kk][1] = Bt3hi[kk][1][0];
        A3hi[kk][2] = Bt3hi[kk][0][1]; A3hi[kk][3] = Bt3hi[kk][1][1];
        A3lo[kk][0] = Bt3lo[kk][0][0]; A3lo[kk][1] = Bt3lo[kk][1][0];
        A3lo[kk][2] = Bt3lo[kk][0][1]; A3lo[kk][3] = Bt3lo[kk][1][1];
    }

    // mm3: x5 = x3*x2   (Bc2 dead after)
    mm_chain(A3hi, A3lo, Bc2hi, Bc2lo, C5);
    V[3] = diag_partial(C5, isdiag, godd);          // tr5
    V[6] = frag_dot(T3, C5);                        // tr8 = tr(x3*x5)

    // B(x3) deferred (C3 kept live instead of 16-reg Bc3)
    uint32_t Bc3hi[2][2][2], Bc3lo[2][2][2];
    conv_to_B(C3, idxA_c, idxB_c, godd, hi16, Bc3hi, Bc3lo);

    // mm4: x6 = x3*x3   (A3, Bc3 dead after)
    mm_chain(A3hi, A3lo, Bc3hi, Bc3lo, C6);
    V[4] = diag_partial(C6, isdiag, godd);          // tr6
    V[5] = frag_dot(Y, C6);                         // tr7 = tr(x*x6)
    V[7] = frag_dot(T3, C6);                        // tr9 = tr(x3*x6); T3 dead

    transpose_frag(C5, idxA_t, idxB_t, godd, T5);
    V[8] = frag_dot(T5, C5);                        // tr10 = tr(x5*x5)
    V[9] = frag_dot(T5, C6);                        // tr11 = tr(x5*x6)

    // ---- 10-value reduce-scatter: 5/3/2/1/1 halving, 12 shfl total ----
    // Final: every lane holds full sum of trace
    //   i = 5*b16 + (b8 ? 3+b4 : (b4 ? 2 : b2))
    const bool b16 = hi16;
    const bool b8 = (lane & 8);
    const bool b4 = (lane & 4);
    const bool b2 = (lane & 2);
    // stage A (xor16): lo half keeps traces 0..4, hi half 5..9
#pragma unroll
    for (int k = 0; k < 5; k++) {
        float send = b16 ? V[k] : V[k + 5];
        float recv = __shfl_xor_sync(0xffffffffu, send, 16);
        V[k] = (b16 ? V[k + 5] : V[k]) + recv;
    }
    // stage B (xor8): b8=0 keeps {0,1,2}, b8=1 keeps {3,4}
#pragma unroll
    for (int k = 0; k < 2; k++) {
        float send = b8 ? V[k] : V[k + 3];
        float recv = __shfl_xor_sync(0xffffffffu, send, 8);
        V[k] = (b8 ? V[k + 3] : V[k]) + recv;
    }
    {
        float recv = __shfl_xor_sync(0xffffffffu, V[2], 8);
        V[2] = V[2] + recv;   // valid in b8=0 lanes
    }
    // stage C (xor4): b8=0: b4=0 keeps {V0,V1}, b4=1 keeps {V2};
    //                 b8=1: b4=0 keeps {V0},    b4=1 keeps {V1}
    {
        float send = b4 ? V[0] : (b8 ? V[1] : V[2]);
        float recv = __shfl_xor_sync(0xffffffffu, send, 4);
        float keep = b4 ? (b8 ? V[1] : V[2]) : V[0];
        V[0] = keep + recv;
    }
    {
        float recv = __shfl_xor_sync(0xffffffffu, V[1], 4);
        V[1] = V[1] + recv;   // valid in b8=0, b4=0 lanes
    }
    // stage D (xor2): only (b8,b4)=(0,0) still has 2 values
    {
        const bool g00 = !b8 && !b4;
        float send = (g00 && !b2) ? V[1] : V[0];
        float recv = __shfl_xor_sync(0xffffffffu, send, 2);
        float keep = (g00 && b2) ? V[1] : V[0];
        V[0] = keep + recv;
    }
    // stage E (xor1)
    V[0] += __shfl_xor_sync(0xffffffffu, V[0], 1);

    // ---- distributed polynomial: canonical lane per trace ----
    {
        const int i = (b16 ? 5 : 0) + (b8 ? (b4 ? 4 : 3) : (b4 ? 2 : (b2 ? 1 : 0)));
        const bool active = ((lane & 1) == 0) &&
                            (((lane & 2) == 0) || ((lane & 12) == 0));
        const float4 cf = __ldg((const float4*)coef + i);
        const float u  = V[0] * (1.0f / 256.0f);
        const float u2 = u * u;
        float term = cf.x * u + cf.y * u2 + cf.z * (u2 * u) + cf.w * (u2 * u2);
        term *= __uint_as_float((uint32_t)(127 - 8 * i) << 23);   // 256^{-i}
        term = active ? term : 0.f;
        // all active lanes are even -> offsets 16,8,4,2 suffice
        term += __shfl_xor_sync(0xffffffffu, term, 16);
        term += __shfl_xor_sync(0xffffffffu, term, 8);
        term += __shfl_xor_sync(0xffffffffu, term, 4);
        term += __shfl_xor_sync(0xffffffffu, term, 2);
        if (lane == 0) out[sample] = term;
    }
}

extern "C" void kernel_launch(void* const* d_in, const int* in_sizes, int n_in,
                              void* d_out, int out_size) {
    const float* x;
    const float* coef;
    if (n_in >= 2 && in_sizes[0] == 40) {
        coef = (const float*)d_in[0];
        x    = (const float*)d_in[1];
    } else {
        x    = (const float*)d_in[0];
        coef = (const float*)d_in[1];
    }
    float* out = (float*)d_out;
    int nsamples = out_size;
    const int warps_per_cta = 4;
    int grid = (nsamples + warps_per_cta - 1) / warps_per_cta;
    acoef_kernel<<<grid, warps_per_cta * 32>>>(x, coef, out, nsamples);
}